// round 11
// baseline (speedup 1.0000x reference)
#include <cuda_runtime.h>
#include <cuda_bf16.h>
#include <cstdint>

// Trajectory signature kernel, v5 (re-bench; round 10 was an infra failure).
// cp.async pipeline + conflict-free LDS.128 reads + shfl_up for previous row.
// Input:  trajectories [4096, 2048, 6] fp32 (row-major)
// Output: [4096, 5] fp32
//
// positions = cumsum(traj[:,:2]); v1/v2 are diffs of it == raw col 0:2
// values -> everything is a consecutive-row-pair reduction.
// One CTA per trajectory. 4 tiles of 512 rows, cp.async triple buffer,
// 2 tiles in flight. Thread t computes rows 2t,2t+1 read as 3 aligned
// float4s (LDS.128, 16B bank-group 3t mod 8 -> conflict-free). Prev row
// comes from lane t-1 via shfl_up; lane 0 reads it from smem (halo at
// tile boundary).

#define T_LEN   2048
#define N_TRAJ  4096
#define TILE    512
#define NT      (T_LEN / TILE)            // 4
#define F4_PER_TILE (TILE * 6 / 4)        // 768
#define HALO_W  8                         // halo words [2..7] hold prev row
#define BUF_WORDS (HALO_W + TILE * 6)     // 3080 words
#define EPS_NORM 1e-6f
#define EPS_MEAN 1e-6f

__device__ __forceinline__ float warp_sum(float x) {
    #pragma unroll
    for (int o = 16; o > 0; o >>= 1)
        x += __shfl_down_sync(0xffffffffu, x, o);
    return x;
}

__device__ __forceinline__ unsigned int smem_u32(const void* p) {
    unsigned int a;
    asm("{ .reg .u64 t; cvta.to.shared.u64 t, %1; cvt.u32.u64 %0, t; }"
        : "=r"(a) : "l"(p));
    return a;
}

#define CP_ASYNC16(dst_u32, src_ptr) \
    asm volatile("cp.async.cg.shared.global [%0], [%1], 16;" \
                 :: "r"(dst_u32), "l"(src_ptr) : "memory")
#define CP_COMMIT() asm volatile("cp.async.commit_group;" ::: "memory")
#define CP_WAIT(n)  asm volatile("cp.async.wait_group %0;" :: "n"(n) : "memory")

__global__ __launch_bounds__(256, 6) void signature_kernel(
    const float4* __restrict__ trajv, float* __restrict__ out)
{
    __shared__ __align__(16) float sb[3][BUF_WORDS];
    __shared__ float red[8][8];

    const int tid  = threadIdx.x;
    const int lane = tid & 31;
    const int tr   = blockIdx.x;
    const float4* base = trajv + (size_t)tr * (T_LEN * 6 / 4);

    // per-buffer smem byte address of float4 slot `tid` (word HALO_W + 4*tid)
    unsigned int dstb[3];
    #pragma unroll
    for (int b = 0; b < 3; ++b)
        dstb[b] = smem_u32(&sb[b][HALO_W + 4 * tid]);

    // prologue: issue tiles 0 and 1
    #pragma unroll
    for (int t = 0; t < 2; ++t) {
        const float4* src = base + t * F4_PER_TILE + tid;
        CP_ASYNC16(dstb[t],               src);
        CP_ASYNC16(dstb[t] + 256 * 16,    src + 256);
        CP_ASYNC16(dstb[t] + 512 * 16,    src + 512);
        CP_COMMIT();
    }

    float s_curv = 0.f, cnt = 0.f;
    float s_vd = 0.f, s_ad = 0.f;
    float s_sp = 0.f, s_sp2 = 0.f;
    float s_f  = 0.f, s_f2  = 0.f;

    #pragma unroll
    for (int t = 0; t < NT; ++t) {
        if (t == NT - 1) { CP_WAIT(0); } else { CP_WAIT(1); }
        __syncthreads();   // tile-t data visible to all; buf (t+2)%3 free

        const int cb = t % 3;

        // issue tile t+2 into buffer (t+2)%3 (overlaps compute below)
        if (t + 2 < NT) {
            const int nb2 = (t + 2) % 3;
            const float4* src = base + (t + 2) * F4_PER_TILE + tid;
            CP_ASYNC16(dstb[nb2],            src);
            CP_ASYNC16(dstb[nb2] + 256 * 16, src + 256);
            CP_ASYNC16(dstb[nb2] + 512 * 16, src + 512);
            CP_COMMIT();
        }

        // halo for tile t+1: copy last row of tile t into next buffer's halo
        if (t + 1 < NT && tid < 6)
            sb[(t + 1) % 3][2 + tid] = sb[cb][HALO_W + (TILE - 1) * 6 + tid];

        // ---- compute rows 2*tid, 2*tid+1 ----
        // 3 aligned float4s: byte offset 32 + 48*tid -> 16B bank-group
        // 3*tid mod 8 -> conflict-free LDS.128.
        const float4* q = reinterpret_cast<const float4*>(&sb[cb][HALO_W + 12 * tid]);
        const float4 q0 = q[0], q1 = q[1], q2 = q[2];
        const float2 p0 = make_float2(q0.x, q0.y), v0 = make_float2(q0.z, q0.w);
        const float2 a0 = make_float2(q1.x, q1.y);
        const float2 p1 = make_float2(q1.z, q1.w), v1 = make_float2(q2.x, q2.y);
        const float2 a1 = make_float2(q2.z, q2.w);

        // previous row (= lane-1's row1) via shuffle; lane 0 reads smem
        float2 pp, pv, pa;
        pp.x = __shfl_up_sync(0xffffffffu, p1.x, 1);
        pp.y = __shfl_up_sync(0xffffffffu, p1.y, 1);
        pv.x = __shfl_up_sync(0xffffffffu, v1.x, 1);
        pv.y = __shfl_up_sync(0xffffffffu, v1.y, 1);
        pa.x = __shfl_up_sync(0xffffffffu, a1.x, 1);
        pa.y = __shfl_up_sync(0xffffffffu, a1.y, 1);
        if (lane == 0) {
            const float2* pb = reinterpret_cast<const float2*>(
                &sb[cb][HALO_W + 12 * tid - 6]);  // tid==0 -> halo words [2..7]
            pp = pb[0]; pv = pb[1]; pa = pb[2];
        }

        // per-row moments (both rows, always valid)
        const float sp0 = sqrtf(v0.x * v0.x + v0.y * v0.y);
        const float sp1 = sqrtf(v1.x * v1.x + v1.y * v1.y);
        const float fo0 = sqrtf(a0.x * a0.x + a0.y * a0.y);
        const float fo1 = sqrtf(a1.x * a1.x + a1.y * a1.y);
        s_sp  += sp0 + sp1;
        s_sp2 = fmaf(sp0, sp0, s_sp2); s_sp2 = fmaf(sp1, sp1, s_sp2);
        s_f   += fo0 + fo1;
        s_f2  = fmaf(fo0, fo0, s_f2);  s_f2  = fmaf(fo1, fo1, s_f2);

        const float nsq0 = p0.x * p0.x + p0.y * p0.y;
        const float nsq1 = p1.x * p1.x + p1.y * p1.y;

        // row1 <- row0 diffs (global r = 512t+2*tid+1 >= 1 always)
        s_vd += fabsf(v1.x - v0.x) + fabsf(v1.y - v0.y);
        s_ad += fabsf(a1.x - a0.x) + fabsf(a1.y - a0.y);

        const bool nf = (t > 0) | (tid > 0);   // rows 0/1 of trajectory excluded
        if (nf) {
            // row0 <- prev diffs
            s_vd += fabsf(v0.x - pv.x) + fabsf(v0.y - pv.y);
            s_ad += fabsf(a0.x - pa.x) + fabsf(a0.y - pa.y);

            // curvature row0 (v1=prev pos delta, v2=row0 pos delta)
            const float nsqp = pp.x * pp.x + pp.y * pp.y;
            const float cr0  = pp.x * p0.y - pp.y * p0.x;
            const float pr0  = nsqp * nsq0;
            if (pr0 > EPS_NORM * EPS_NORM) {
                s_curv = fmaf(fabsf(cr0), rsqrtf(pr0), s_curv);
                cnt += 1.0f;
            }
            // curvature row1
            const float cr1 = p0.x * p1.y - p0.y * p1.x;
            const float pr1 = nsq0 * nsq1;
            if (pr1 > EPS_NORM * EPS_NORM) {
                s_curv = fmaf(fabsf(cr1), rsqrtf(pr1), s_curv);
                cnt += 1.0f;
            }
        }
    }

    // reductions
    s_curv = warp_sum(s_curv);
    cnt    = warp_sum(cnt);
    s_vd   = warp_sum(s_vd);
    s_ad   = warp_sum(s_ad);
    s_sp   = warp_sum(s_sp);
    s_sp2  = warp_sum(s_sp2);
    s_f    = warp_sum(s_f);
    s_f2   = warp_sum(s_f2);

    const int wid = tid >> 5;
    if (lane == 0) {
        red[wid][0] = s_curv; red[wid][1] = cnt;
        red[wid][2] = s_vd;   red[wid][3] = s_ad;
        red[wid][4] = s_sp;   red[wid][5] = s_sp2;
        red[wid][6] = s_f;    red[wid][7] = s_f2;
    }
    __syncthreads();

    if (tid == 0) {
        float t_curv = 0.f, t_cnt = 0.f, t_vd = 0.f, t_ad = 0.f;
        float t_sp = 0.f, t_sp2 = 0.f, t_f = 0.f, t_f2 = 0.f;
        #pragma unroll
        for (int w = 0; w < 8; ++w) {
            t_curv += red[w][0]; t_cnt += red[w][1];
            t_vd   += red[w][2]; t_ad  += red[w][3];
            t_sp   += red[w][4]; t_sp2 += red[w][5];
            t_f    += red[w][6]; t_f2  += red[w][7];
        }

        const float path_curvature = (t_cnt > 0.f) ? (t_curv / t_cnt) : 0.f;

        const float denom = 2.0f * (float)(T_LEN - 1);
        const float velocity_smoothness = 1.0f / (1.0f + t_vd / denom);
        const float acceleration_jerk   = t_ad / denom;

        const float msp = t_sp / (float)T_LEN;
        float var_sp = t_sp2 / (float)T_LEN - msp * msp;
        if (var_sp < 0.f) var_sp = 0.f;
        const float movement_rhythm = sqrtf(var_sp) / (msp + EPS_MEAN);

        const float mf = t_f / (float)T_LEN;
        float var_f = t_f2 / (float)T_LEN - mf * mf;
        if (var_f < 0.f) var_f = 0.f;
        const float force_modulation = sqrtf(var_f) / (mf + EPS_MEAN);

        float* o = out + tr * 5;
        o[0] = path_curvature;
        o[1] = velocity_smoothness;
        o[2] = acceleration_jerk;
        o[3] = movement_rhythm;
        o[4] = force_modulation;
    }
}

extern "C" void kernel_launch(void* const* d_in, const int* in_sizes, int n_in,
                              void* d_out, int out_size) {
    const float4* traj = (const float4*)d_in[0];
    float* out = (float*)d_out;
    signature_kernel<<<N_TRAJ, 256>>>(traj, out);
}